// round 11
// baseline (speedup 1.0000x reference)
#include <cuda_runtime.h>
#include <math.h>

#define BB   8
#define HH   256
#define WW   256
#define HW   (HH*WW)
#define RPB  2
#define VR   8                    // vertical prefix radius
#define NBLK (BB*HH/RPB)          // 1024 blocks, 128 per image

// Scratch (no device allocations allowed): per-block partials + ticket.
__device__ float    g_pp[NBLK];
__device__ float    g_pw[NBLK];
__device__ float    g_pc[NBLK];
__device__ unsigned g_ticket;     // zero-init; last block resets to 0

// ---------------------------------------------------------------------------
// Fused kernel: one block per 2 rows (same image), one thread per column.
//  - Prologue issues ALL gmem loads together (4 logits + 18 target rows):
//    one latency wall covers the whole kernel.
//  - Vertical r=1..8 prefix masks from registers (exact; clamped bits only
//    re-assert facts from <= radii, so ffs returns the true minimum).
//    Warp-level serial-tail probability ~0.2% (needs 17 identical rows).
//  - Horizontal envelope: prefix r<=4 unconditional, batched chunk r=5..8
//    conditional (one LDS wall), serial bounds-checked tail r>=9 (~0.1%).
//    Bit-exact vs reference (order-independent min, monotone rounding).
//  - Ballot counts, 2-var reduction tree, last-block global reduction
//    (threadfence + ticket; deterministic summation order).
// ---------------------------------------------------------------------------
__global__ void __launch_bounds__(256) fused_kernel(
    const float* __restrict__ logits, const int* __restrict__ targets,
    float* __restrict__ out) {
    int blk = blockIdx.x;          // 0..1023
    int b   = blk >> 7;            // image
    int h0  = (blk & 127) * RPB;   // first of 2 rows
    int w   = threadIdx.x;

    const int* tcol = targets + b * HW + w;   // column w, stride WW

    // ---- prologue: issue ALL gmem loads together ----
    float l0_[RPB], l1_[RPB];
#pragma unroll
    for (int i = 0; i < RPB; i++) {
        l0_[i] = logits[((b * 2 + 0) * HH + (h0 + i)) * WW + w];
        l1_[i] = logits[((b * 2 + 1) * HH + (h0 + i)) * WW + w];
    }

    int t[RPB + 2 * VR];           // rows h0-8 .. h0+RPB+7
    if (h0 >= VR && h0 + RPB + VR - 1 < HH) { // interior: no clamping
#pragma unroll
        for (int j = 0; j < RPB + 2 * VR; j++) t[j] = tcol[(h0 - VR + j) * WW];
    } else {
#pragma unroll
        for (int j = 0; j < RPB + 2 * VR; j++) {
            int hh = min(max(h0 - VR + j, 0), HH - 1);
            t[j] = tcol[hh * WW];
        }
    }

    __shared__ float2 srow[RPB][WW + 16];     // +-8 BIG pads
    if (w < 8) {
#pragma unroll
        for (int i = 0; i < RPB; i++) {
            srow[i][w]          = make_float2(1e9f, 1e9f);
            srow[i][WW + 8 + w] = make_float2(1e9f, 1e9f);
        }
    }

    float d2p_[RPB], d2n_[RPB];
    int   me_[RPB];

#pragma unroll
    for (int i = 0; i < RPB; i++) {
        int hl = i + VR;
        int me = t[hl];
        me_[i] = me;
        unsigned m1 = 0, m0 = 0;
#pragma unroll
        for (int r = 1; r <= VR; r++) {
            int o = t[hl - r] | t[hl + r];
            int a = t[hl - r] & t[hl + r];
            m1 |= (unsigned)o << (r - 1);
            m0 |= (unsigned)(a ^ 1) << (r - 1);
        }
        int r1 = me        ? 0 : (m1 ? __ffs(m1) : 512);
        int r0 = (me == 0) ? 0 : (m0 ? __ffs(m0) : 512);

        if ((r1 | r0) >= 512) {               // ~0.2% of warps: exact serial tail
            int h = h0 + i;
#pragma unroll 1
            for (int r = VR + 1; r < HH; r++) {
                if ((r1 | r0) < 512) break;
                int tu = tcol[max(h - r, 0) * WW];
                int td = tcol[min(h + r, HH - 1) * WW];
                if (r1 == 512 && (tu | td))      r1 = r;
                if (r0 == 512 && (tu & td) == 0) r0 = r;
            }
        }
        d2p_[i] = (r1 <= 255) ? (float)(r1 * r1) : 1e9f;
        d2n_[i] = (r0 <= 255) ? (float)(r0 * r0) : 1e9f;
        srow[i][8 + w] = make_float2(d2p_[i], d2n_[i]);
    }
    __syncthreads();

    // sigmoid while other warps are in the barrier / LDS phase
    float pred_[RPB];
#pragma unroll
    for (int i = 0; i < RPB; i++)
        pred_[i] = __fdividef(1.0f, 1.0f + __expf(l0_[i] - l1_[i]));

    float accP = 0.f, accW = 0.f;

#pragma unroll
    for (int i = 0; i < RPB; i++) {
        const float2* c = &srow[i][8 + w];
        float bp = d2p_[i], bn = d2n_[i];

        // unconditional prefix r=1..4 (8 independent LDS.64, one wall)
        float2 L1 = c[-1], R1 = c[1];
        float2 L2 = c[-2], R2 = c[2];
        float2 L3 = c[-3], R3 = c[3];
        float2 L4 = c[-4], R4 = c[4];
        bp = fminf(bp, fminf(L1.x, R1.x) + 1.0f);  bn = fminf(bn, fminf(L1.y, R1.y) + 1.0f);
        bp = fminf(bp, fminf(L2.x, R2.x) + 4.0f);  bn = fminf(bn, fminf(L2.y, R2.y) + 4.0f);
        bp = fminf(bp, fminf(L3.x, R3.x) + 9.0f);  bn = fminf(bn, fminf(L3.y, R3.y) + 9.0f);
        bp = fminf(bp, fminf(L4.x, R4.x) + 16.0f); bn = fminf(bn, fminf(L4.y, R4.y) + 16.0f);

        if (fmaxf(bp, bn) > 25.0f) {
            // conditional batched chunk r=5..8 (one LDS wall)
            float2 L5 = c[-5], R5 = c[5];
            float2 L6 = c[-6], R6 = c[6];
            float2 L7 = c[-7], R7 = c[7];
            float2 L8 = c[-8], R8 = c[8];
            bp = fminf(bp, fminf(L5.x, R5.x) + 25.0f); bn = fminf(bn, fminf(L5.y, R5.y) + 25.0f);
            bp = fminf(bp, fminf(L6.x, R6.x) + 36.0f); bn = fminf(bn, fminf(L6.y, R6.y) + 36.0f);
            bp = fminf(bp, fminf(L7.x, R7.x) + 49.0f); bn = fminf(bn, fminf(L7.y, R7.y) + 49.0f);
            bp = fminf(bp, fminf(L8.x, R8.x) + 64.0f); bn = fminf(bn, fminf(L8.y, R8.y) + 64.0f);

            if (fmaxf(bp, bn) > 81.0f) {      // ~0.1% of warps: exact serial tail
#pragma unroll 1
                for (int r = 9; r < WW; r++) {
                    float rr = (float)(r * r);
                    if (rr >= bp && rr >= bn) break;
                    if (w - r >= 0) {
                        float2 a = srow[i][8 + w - r];
                        bp = fminf(bp, a.x + rr); bn = fminf(bn, a.y + rr);
                    }
                    if (w + r < WW) {
                        float2 d = srow[i][8 + w + r];
                        bp = fminf(bp, d.x + rr); bn = fminf(bn, d.y + rr);
                    }
                }
            }
        }

        accP += pred_[i];
        accW += pred_[i] * (sqrtf(bp) - sqrtf(bn));
    }

    // ---- warp counts via ballots (warp-uniform) ----
    unsigned m = 0xFFFFFFFFu;
    int wcnt = 0;
#pragma unroll
    for (int i = 0; i < RPB; i++)
        wcnt += __popc(__ballot_sync(m, me_[i]));
    float cv = (float)wcnt;

    // ---- deterministic block reduction (2 shuffled vars) ----
#pragma unroll
    for (int o = 16; o > 0; o >>= 1) {
        accP += __shfl_down_sync(m, accP, o);
        accW += __shfl_down_sync(m, accW, o);
    }
    __shared__ float rr0[8], rr1[8], rr2[8];
    if ((w & 31) == 0) {
        rr0[w >> 5] = accP; rr1[w >> 5] = accW; rr2[w >> 5] = cv;
    }
    __syncthreads();

    __shared__ bool s_last;
    if (w == 0) {
        float s0 = 0.f, s1 = 0.f, s2 = 0.f;
#pragma unroll
        for (int i = 0; i < 8; i++) { s0 += rr0[i]; s1 += rr1[i]; s2 += rr2[i]; }
        g_pp[blk] = s0;
        g_pw[blk] = s1;
        g_pc[blk] = s2;
        __threadfence();
        unsigned tk = atomicAdd(&g_ticket, 1u);
        s_last = (tk == (unsigned)(NBLK - 1));
    }
    __syncthreads();
    if (!s_last) return;

    // ---- last block: global reduction (deterministic order) ----
    int wb   = w >> 5;             // batch handled by this warp
    int lane = w & 31;
    int base = wb * 128;           // 128 partials per image
    float s0 = 0.f, s1 = 0.f, s2 = 0.f;
#pragma unroll
    for (int i = 0; i < 4; i++) {
        int idx = base + lane + i * 32;
        s0 += __ldcg(&g_pp[idx]);
        s1 += __ldcg(&g_pw[idx]);
        s2 += __ldcg(&g_pc[idx]);
    }
#pragma unroll
    for (int o = 16; o > 0; o >>= 1) {
        s0 += __shfl_down_sync(m, s0, o);
        s1 += __shfl_down_sync(m, s1, o);
        s2 += __shfl_down_sync(m, s2, o);
    }
    __shared__ float pb[8];
    if (lane == 0) {
        float inv = 1.0f / (float)HW;
        float mean_pred = s0 * inv;
        float mean_w    = s1 * inv;
        float per_b;
        if (s2 == 0.0f)           per_b = mean_pred;
        else if (s2 == (float)HW) per_b = 1.0f - mean_pred;
        else                      per_b = mean_w;
        pb[wb] = per_b;
    }
    __syncthreads();
    if (w == 0) {
        float total = 0.f;
#pragma unroll
        for (int i = 0; i < BB; i++) total += pb[i];
        out[0] = total / (float)BB;
        g_ticket = 0;                          // reset for next graph replay
    }
}

extern "C" void kernel_launch(void* const* d_in, const int* in_sizes, int n_in,
                              void* d_out, int out_size) {
    const float* logits  = (const float*)d_in[0];
    const int*   targets = (const int*)d_in[1];
    float*       out     = (float*)d_out;

    fused_kernel<<<NBLK, 256>>>(logits, targets, out);
}